// round 11
// baseline (speedup 1.0000x reference)
#include <cuda_runtime.h>
#include <cuda_fp16.h>
#include <math.h>
#include <stdint.h>

#define BB 32
#define CC 256
#define NN 3136
#define OUTC 32896            // 256*257/2
#define MATSZ (BB*CC*CC)
#define XSZ (BB*CC*NN)

#define CHK 32
#define STG64 16384           // gram stage: A(8K)+B(8K)
#define SMEM64 (3*STG64)      // 49152
#define STG32 12288           // ns stage: A(8K)+B(4K)
#define SMEM32 (3*STG32)      // 36864
#define NBG 2                 // batches per ns CTA
#define SSCALE 64.0f
#define INVS2 (1.0f/(SSCALE*SSCALE))

// gram: 10 upper 64x64 tiles
__device__ __constant__ int c_TI[10] = {0,0,0,0,1,1,1,2,2,3};
__device__ __constant__ int c_TJ[10] = {0,1,2,3,1,2,3,2,3,3};
// ns: 20 tiles 64x32 with j*32 >= i*64
__device__ __constant__ int c_SI[20] = {0,0,0,0,0,0,0,0, 1,1,1,1,1,1, 2,2,2,2, 3,3};
__device__ __constant__ int c_SJ[20] = {0,1,2,3,4,5,6,7, 2,3,4,5,6,7, 4,5,6,7, 6,7};

// ---------------- scratch: matrices stored as hi/lo fp16 pairs ----------------
// slots: A=0 B0=1 B1=2 Y0=3 Y1=4 Z0=5 Z1=6
__device__ __align__(16) __half g_H[7*MATSZ];
__device__ __align__(16) __half g_L[7*MATSZ];
__device__ __align__(16) __half g_Xh[XSZ];
__device__ __align__(16) __half g_Xl[XSZ];
__device__ float g_s[BB*CC];
__device__ float g_q[BB*CC];
__device__ float g_tr[BB];

// ---------------- primitives ----------------
__device__ __forceinline__ uint32_t smem_u32(const void* p) {
    uint32_t a;
    asm("{ .reg .u64 t; cvta.to.shared.u64 t, %1; cvt.u32.u64 %0, t; }" : "=r"(a) : "l"(p));
    return a;
}

__device__ __forceinline__ void mma16(float* c, const unsigned* a, const unsigned* b) {
    asm volatile(
        "mma.sync.aligned.m16n8k16.row.col.f32.f16.f16.f32 "
        "{%0,%1,%2,%3}, {%4,%5,%6,%7}, {%8,%9}, {%0,%1,%2,%3};"
        : "+f"(c[0]), "+f"(c[1]), "+f"(c[2]), "+f"(c[3])
        : "r"(a[0]), "r"(a[1]), "r"(a[2]), "r"(a[3]), "r"(b[0]), "r"(b[1]));
}

__device__ __forceinline__ void ldm4(unsigned r[4], uint32_t a) {
    asm volatile("ldmatrix.sync.aligned.m8n8.x4.shared.b16 {%0,%1,%2,%3}, [%4];"
                 : "=r"(r[0]), "=r"(r[1]), "=r"(r[2]), "=r"(r[3]) : "r"(a));
}

#define CP16(dst, src) \
    asm volatile("cp.async.cg.shared.global [%0], [%1], 16;" :: "r"(dst), "l"(src))
#define CP_COMMIT() asm volatile("cp.async.commit_group;" ::: "memory")
#define CP_WAIT1() asm volatile("cp.async.wait_group 1;" ::: "memory")

__device__ __forceinline__ void split_pair(float v0, float v1, unsigned& hi, unsigned& lo) {
    float s0 = v0 * SSCALE, s1 = v1 * SSCALE;
    __half h0 = __float2half_rn(s0), h1 = __float2half_rn(s1);
    __half l0 = __float2half_rn(s0 - __half2float(h0));
    __half l1 = __float2half_rn(s1 - __half2float(h1));
    __half2 hh = __halves2half2(h0, h1), ll = __halves2half2(l0, l1);
    hi = *(unsigned*)&hh;
    lo = *(unsigned*)&ll;
}

// ================= 64x64 path (gram, pipelined) =================
__device__ __forceinline__ void issue_chunk64(uint32_t dstBase,
                                              const __half* Ah, const __half* Al,
                                              const __half* Bh, const __half* Bl,
                                              int strideH, int k0, int tid) {
#pragma unroll
    for (int i = 0; i < 8; ++i) {
        int n = i * 128 + tid;
        int mat = n >> 9;
        int m = n & 511;
        int row = m >> 3, g = m & 7;
        const __half* hbase = (mat == 0) ? (g < 4 ? Ah : Al) : (g < 4 ? Bh : Bl);
        const __half* src = hbase + (size_t)row * strideH + k0 + 8 * (g & 3);
        uint32_t dst = dstBase + mat * 8192 + row * 128 + ((g ^ (row & 7)) << 4);
        CP16(dst, src);
    }
}

__device__ __forceinline__ void compute_chunk64(uint32_t stBase, float acc[2][4][4],
                                                int wm, int wn, int lane) {
    int lr = lane & 7;
    int lt8 = (lane >> 3) & 1;
    int lkh = (lane >> 4) & 1;
    uint32_t aL = stBase + (wm * 32 + lt8 * 8 + lr) * 128;
    uint32_t bL = stBase + 8192 + (wn * 32 + lkh * 8 + lr) * 128;
#pragma unroll
    for (int ks = 0; ks < 2; ++ks) {
        unsigned ah[2][4], al[2][4], bh[2][4], bl[2][4];
        int gA = ks * 2 + lkh, gB = ks * 2 + lt8;
        ldm4(ah[0], aL + ((gA ^ lr) << 4));
        ldm4(ah[1], aL + 2048 + ((gA ^ lr) << 4));
        ldm4(al[0], aL + (((gA + 4) ^ lr) << 4));
        ldm4(al[1], aL + 2048 + (((gA + 4) ^ lr) << 4));
        ldm4(bh[0], bL + ((gB ^ lr) << 4));
        ldm4(bh[1], bL + 2048 + ((gB ^ lr) << 4));
        ldm4(bl[0], bL + (((gB + 4) ^ lr) << 4));
        ldm4(bl[1], bL + 2048 + (((gB + 4) ^ lr) << 4));
#pragma unroll
        for (int it = 0; it < 2; ++it)
#pragma unroll
            for (int jt = 0; jt < 4; ++jt)
                mma16(acc[it][jt], ah[it], &bh[jt >> 1][(jt & 1) * 2]);
#pragma unroll
        for (int it = 0; it < 2; ++it)
#pragma unroll
            for (int jt = 0; jt < 4; ++jt)
                mma16(acc[it][jt], ah[it], &bl[jt >> 1][(jt & 1) * 2]);
#pragma unroll
        for (int it = 0; it < 2; ++it)
#pragma unroll
            for (int jt = 0; jt < 4; ++jt)
                mma16(acc[it][jt], al[it], &bh[jt >> 1][(jt & 1) * 2]);
    }
}

__device__ __forceinline__ void run_loop64(uint32_t smem_u,
                                           const __half* Ah, const __half* Al,
                                           const __half* Bh, const __half* Bl,
                                           int strideH, int nch, float acc[2][4][4],
                                           int wm, int wn, int lane, int tid) {
    issue_chunk64(smem_u, Ah, Al, Bh, Bl, strideH, 0, tid);
    CP_COMMIT();
    issue_chunk64(smem_u + STG64, Ah, Al, Bh, Bl, strideH, CHK, tid);
    CP_COMMIT();
    int st = 0;
    for (int s = 0; s < nch; ++s) {
        CP_WAIT1();
        __syncthreads();
        if (s + 2 < nch) {
            int st2 = st + 2;
            if (st2 >= 3) st2 -= 3;
            issue_chunk64(smem_u + st2 * STG64, Ah, Al, Bh, Bl, strideH, (s + 2) * CHK, tid);
        }
        CP_COMMIT();
        compute_chunk64(smem_u + st * STG64, acc, wm, wn, lane);
        if (++st == 3) st = 0;
    }
}

// ================= 64x32 path (NS GEMMs, b-grouped pipeline) =================
__device__ __forceinline__ void issue_chunk32(uint32_t dstBase,
                                              const __half* Ph, const __half* Pl,
                                              const __half* Qh, const __half* Ql,
                                              int k0, int tid) {
#pragma unroll
    for (int i = 0; i < 6; ++i) {
        int n = i * 128 + tid;          // 0..767
        bool isB = n >= 512;
        int m = isB ? n - 512 : n;
        int row = m >> 3, g = m & 7;
        const __half* hbase = isB ? (g < 4 ? Qh : Ql) : (g < 4 ? Ph : Pl);
        const __half* src = hbase + (size_t)row * CC + k0 + 8 * (g & 3);
        uint32_t dst = dstBase + (isB ? 8192 : 0) + row * 128 + ((g ^ (row & 7)) << 4);
        CP16(dst, src);
    }
}

__device__ __forceinline__ void compute_chunk32(uint32_t stBase, float acc[2][2][4],
                                                int wm, int wn, int lane) {
    int lr = lane & 7;
    int lt8 = (lane >> 3) & 1;
    int lkh = (lane >> 4) & 1;
    uint32_t aL = stBase + (wm * 32 + lt8 * 8 + lr) * 128;
    uint32_t bL = stBase + 8192 + (wn * 16 + lkh * 8 + lr) * 128;
#pragma unroll
    for (int ks = 0; ks < 2; ++ks) {
        unsigned ah[2][4], al[2][4], bh[4], bl[4];
        int gA = ks * 2 + lkh, gB = ks * 2 + lt8;
        ldm4(ah[0], aL + ((gA ^ lr) << 4));
        ldm4(ah[1], aL + 2048 + ((gA ^ lr) << 4));
        ldm4(al[0], aL + (((gA + 4) ^ lr) << 4));
        ldm4(al[1], aL + 2048 + (((gA + 4) ^ lr) << 4));
        ldm4(bh, bL + ((gB ^ lr) << 4));
        ldm4(bl, bL + (((gB + 4) ^ lr) << 4));
#pragma unroll
        for (int it = 0; it < 2; ++it)
#pragma unroll
            for (int jt = 0; jt < 2; ++jt)
                mma16(acc[it][jt], ah[it], &bh[jt * 2]);
#pragma unroll
        for (int it = 0; it < 2; ++it)
#pragma unroll
            for (int jt = 0; jt < 2; ++jt)
                mma16(acc[it][jt], ah[it], &bl[jt * 2]);
#pragma unroll
        for (int it = 0; it < 2; ++it)
#pragma unroll
            for (int jt = 0; jt < 2; ++jt)
                mma16(acc[it][jt], al[it], &bh[jt * 2]);
    }
}

// ---------------- splitx + trace ----------------
__global__ __launch_bounds__(256) void splitx_kernel(const float* __restrict__ X,
                                                     __half* __restrict__ Xh,
                                                     __half* __restrict__ Xl,
                                                     float* __restrict__ s,
                                                     float* __restrict__ q) {
    int c = blockIdx.x, b = blockIdx.y;
    size_t base = ((size_t)b * CC + c) * NN;
    const float4* row = (const float4*)(X + base);
    float acc = 0.f, accq = 0.f;
    for (int i = threadIdx.x; i < NN / 4; i += 256) {
        float4 v = row[i];
        acc += v.x + v.y + v.z + v.w;
        accq += v.x * v.x + v.y * v.y + v.z * v.z + v.w * v.w;
        unsigned h0, l0, h1, l1;
        split_pair(v.x, v.y, h0, l0);
        split_pair(v.z, v.w, h1, l1);
        *(uint2*)(Xh + base + i * 4) = make_uint2(h0, h1);
        *(uint2*)(Xl + base + i * 4) = make_uint2(l0, l1);
    }
    __shared__ float ss[256], sq[256];
    ss[threadIdx.x] = acc;
    sq[threadIdx.x] = accq;
    __syncthreads();
    for (int st = 128; st > 0; st >>= 1) {
        if (threadIdx.x < st) {
            ss[threadIdx.x] += ss[threadIdx.x + st];
            sq[threadIdx.x] += sq[threadIdx.x + st];
        }
        __syncthreads();
    }
    if (threadIdx.x == 0) {
        s[b * CC + c] = ss[0];
        q[b * CC + c] = sq[0];
    }
}

__global__ __launch_bounds__(256) void trred_kernel(const float* __restrict__ s,
                                                    const float* __restrict__ q,
                                                    float* __restrict__ tr) {
    int b = blockIdx.x, c = threadIdx.x;
    const float inv_n = 1.0f / (float)NN;
    const float inv_n2 = inv_n * inv_n;
    float sv = s[b * CC + c];
    float v = q[b * CC + c] * inv_n - sv * sv * inv_n2;
    __shared__ float sm[256];
    sm[c] = v;
    __syncthreads();
    for (int st = 128; st > 0; st >>= 1) {
        if (c < st) sm[c] += sm[c + st];
        __syncthreads();
    }
    if (c == 0) tr[b] = sm[0];
}

// ---------------- gram ----------------
__global__ __launch_bounds__(128, 4) void gram_mma(const __half* __restrict__ Xh,
                                                   const __half* __restrict__ Xl,
                                                   const float* __restrict__ sv,
                                                   const float* __restrict__ trv,
                                                   __half* __restrict__ H,
                                                   __half* __restrict__ L) {
    extern __shared__ unsigned swm[];
    uint32_t smem_u = smem_u32(swm);
    int b = blockIdx.z, tile = blockIdx.x;
    int i0 = c_TI[tile] * 64, j0 = c_TJ[tile] * 64;
    bool mirror = (i0 != j0);
    int tid = threadIdx.x;
    int warp = tid >> 5, lane = tid & 31;
    int wm = warp >> 1, wn = warp & 1, g = lane >> 2, t = lane & 3;
    float acc[2][4][4] = {};

    const __half* Xhb = Xh + (size_t)b * CC * NN;
    const __half* Xlb = Xl + (size_t)b * CC * NN;
    run_loop64(smem_u, Xhb + (size_t)i0 * NN, Xlb + (size_t)i0 * NN,
               Xhb + (size_t)j0 * NN, Xlb + (size_t)j0 * NN, NN, NN / CHK,
               acc, wm, wn, lane, tid);

    const float inv_n = 1.0f / (float)NN;
    const float inv_n2 = inv_n * inv_n;
    float invtr = 1.0f / trv[b];
    float c1 = INVS2 * inv_n * invtr;
    float c2 = inv_n2 * invtr;
    __half* Ah = H + (size_t)b * CC * CC;
    __half* Al = L + (size_t)b * CC * CC;
    __half* B0h = H + (size_t)MATSZ + (size_t)b * CC * CC;
    __half* B0l = L + (size_t)MATSZ + (size_t)b * CC * CC;
#pragma unroll
    for (int it = 0; it < 2; ++it)
#pragma unroll
        for (int jt = 0; jt < 4; ++jt) {
            int gi = i0 + wm * 32 + it * 16 + g;
            int gj = j0 + wn * 32 + jt * 8 + 2 * t;
            float* ca = acc[it][jt];
#pragma unroll
            for (int h = 0; h < 2; ++h) {
                int r = gi + h * 8;
                float si = sv[b * CC + r];
                float a0 = ca[h * 2 + 0] * c1 - si * sv[b * CC + gj] * c2;
                float a1 = ca[h * 2 + 1] * c1 - si * sv[b * CC + gj + 1] * c2;
                float w0 = (r == gj ? 1.5f : 0.0f) - 0.5f * a0;
                float w1 = (r == gj + 1 ? 1.5f : 0.0f) - 0.5f * a1;
                unsigned hi, lo;
                split_pair(a0, a1, hi, lo);
                *(unsigned*)&Ah[(size_t)r * CC + gj] = hi;
                *(unsigned*)&Al[(size_t)r * CC + gj] = lo;
                split_pair(w0, w1, hi, lo);
                *(unsigned*)&B0h[(size_t)r * CC + gj] = hi;
                *(unsigned*)&B0l[(size_t)r * CC + gj] = lo;
                if (mirror) {
                    float v[2] = {a0, a1};
                    float w[2] = {w0, w1};
#pragma unroll
                    for (int e = 0; e < 2; ++e) {
                        float sa = v[e] * SSCALE;
                        __half ha = __float2half_rn(sa);
                        Ah[(size_t)(gj + e) * CC + r] = ha;
                        Al[(size_t)(gj + e) * CC + r] = __float2half_rn(sa - __half2float(ha));
                        float sw = w[e] * SSCALE;
                        __half hw = __float2half_rn(sw);
                        B0h[(size_t)(gj + e) * CC + r] = hw;
                        B0l[(size_t)(gj + e) * CC + r] = __float2half_rn(sw - __half2float(hw));
                    }
                }
            }
        }
}

// ---------------- NS GEMM (64x32, b-grouped ×2, slot-indexed, optional pair via grid.y) ----------------
// EPI 0: C=P@Q     EPI 1: C=1.5I-0.5(P@Q)     EPI 2: triuvec(P@Q * sqrt(tr))
template <int EPI>
__global__ __launch_bounds__(128, 5) void ns_mma(__half* __restrict__ H,
                                                 __half* __restrict__ L,
                                                 int p0, int q0, int cs0,
                                                 int p1, int q1, int cs1,
                                                 const float* __restrict__ trv,
                                                 float* __restrict__ outg) {
    extern __shared__ unsigned swm[];
    uint32_t smem_u = smem_u32(swm);
    int tile = blockIdx.x;
    int sel = blockIdx.y;
    int ps = sel ? p1 : p0, qs = sel ? q1 : q0, cs = sel ? cs1 : cs0;
    int i0 = c_SI[tile] * 64, j0 = c_SJ[tile] * 32;
    int tid = threadIdx.x;
    int warp = tid >> 5, lane = tid & 31;
    int wm = warp >> 1, wn = warp & 1, g = lane >> 2, t = lane & 3;
    int b0 = blockIdx.z * NBG;

    const __half *Ph[NBG], *Pl[NBG], *Qh[NBG], *Ql[NBG];
#pragma unroll
    for (int e = 0; e < NBG; ++e) {
        size_t mb = (size_t)(b0 + e) * CC * CC;
        Ph[e] = H + (size_t)ps * MATSZ + mb + (size_t)i0 * CC;
        Pl[e] = L + (size_t)ps * MATSZ + mb + (size_t)i0 * CC;
        Qh[e] = H + (size_t)qs * MATSZ + mb + (size_t)j0 * CC;
        Ql[e] = L + (size_t)qs * MATSZ + mb + (size_t)j0 * CC;
    }

    float acc[2][2][4] = {};
    const int TOT = NBG * 8;   // 16 chunks across both batches

    issue_chunk32(smem_u, Ph[0], Pl[0], Qh[0], Ql[0], 0, tid);
    CP_COMMIT();
    issue_chunk32(smem_u + STG32, Ph[0], Pl[0], Qh[0], Ql[0], CHK, tid);
    CP_COMMIT();

    int st = 0;
    for (int u = 0; u < TOT; ++u) {
        CP_WAIT1();
        __syncthreads();
        int un = u + 2;
        if (un < TOT) {
            int e = un >> 3;
            int st2 = st + 2;
            if (st2 >= 3) st2 -= 3;
            issue_chunk32(smem_u + st2 * STG32, Ph[e], Pl[e], Qh[e], Ql[e],
                          (un & 7) * CHK, tid);
        }
        CP_COMMIT();
        compute_chunk32(smem_u + st * STG32, acc, wm, wn, lane);
        if (++st == 3) st = 0;

        if ((u & 7) == 7) {
            // epilogue for batch b = b0 + (u>>3); per-warp independent, no sync needed
            int b = b0 + (u >> 3);
            size_t mb = (size_t)b * CC * CC;
            __half* Ch = H + (size_t)cs * MATSZ + mb;
            __half* Cl = L + (size_t)cs * MATSZ + mb;
            float scale = (EPI == 2) ? sqrtf(trv[b]) * INVS2 : INVS2;
#pragma unroll
            for (int it = 0; it < 2; ++it)
#pragma unroll
                for (int jt = 0; jt < 2; ++jt) {
                    int gi = i0 + wm * 32 + it * 16 + g;
                    int gj = j0 + wn * 16 + jt * 8 + 2 * t;
                    float* ca = acc[it][jt];
#pragma unroll
                    for (int h = 0; h < 2; ++h) {
                        int r = gi + h * 8;
                        if (EPI == 2) {
                            float v0 = ca[h * 2 + 0] * scale, v1 = ca[h * 2 + 1] * scale;
                            int base = r * CC - (r * (r - 1)) / 2 - r;
                            if (gj >= r) outg[(size_t)b * OUTC + base + gj] = v0;
                            if (gj + 1 >= r) outg[(size_t)b * OUTC + base + gj + 1] = v1;
                        } else {
                            float v0 = ca[h * 2 + 0] * INVS2, v1 = ca[h * 2 + 1] * INVS2;
                            if (EPI == 1) {
                                v0 = (r == gj ? 1.5f : 0.0f) - 0.5f * v0;
                                v1 = (r == gj + 1 ? 1.5f : 0.0f) - 0.5f * v1;
                            }
                            unsigned hi, lo;
                            split_pair(v0, v1, hi, lo);
                            *(unsigned*)&Ch[(size_t)r * CC + gj] = hi;
                            *(unsigned*)&Cl[(size_t)r * CC + gj] = lo;
                            float v[2] = {v0, v1};
#pragma unroll
                            for (int e2 = 0; e2 < 2; ++e2) {
                                int c = gj + e2;
                                if (c > r) {
                                    float sv2 = v[e2] * SSCALE;
                                    __half hh = __float2half_rn(sv2);
                                    Ch[(size_t)c * CC + r] = hh;
                                    Cl[(size_t)c * CC + r] =
                                        __float2half_rn(sv2 - __half2float(hh));
                                }
                            }
                        }
                    }
                }
            // reset accumulators for next batch
#pragma unroll
            for (int it = 0; it < 2; ++it)
#pragma unroll
                for (int jt = 0; jt < 2; ++jt)
#pragma unroll
                    for (int e2 = 0; e2 < 4; ++e2) acc[it][jt][e2] = 0.f;
        }
    }
}

// ---------------- launch ----------------
extern "C" void kernel_launch(void* const* d_in, const int* in_sizes, int n_in,
                              void* d_out, int out_size) {
    const float* x = (const float*)d_in[0];
    float* out = (float*)d_out;

    __half *H, *L, *Xh, *Xl;
    float *s, *q, *tr;
    cudaGetSymbolAddress((void**)&H, g_H);
    cudaGetSymbolAddress((void**)&L, g_L);
    cudaGetSymbolAddress((void**)&Xh, g_Xh);
    cudaGetSymbolAddress((void**)&Xl, g_Xl);
    cudaGetSymbolAddress((void**)&s, g_s);
    cudaGetSymbolAddress((void**)&q, g_q);
    cudaGetSymbolAddress((void**)&tr, g_tr);

    cudaFuncSetAttribute(gram_mma, cudaFuncAttributeMaxDynamicSharedMemorySize, SMEM64);
    cudaFuncSetAttribute(ns_mma<0>, cudaFuncAttributeMaxDynamicSharedMemorySize, SMEM32);
    cudaFuncSetAttribute(ns_mma<1>, cudaFuncAttributeMaxDynamicSharedMemorySize, SMEM32);
    cudaFuncSetAttribute(ns_mma<2>, cudaFuncAttributeMaxDynamicSharedMemorySize, SMEM32);

    splitx_kernel<<<dim3(CC, BB), 256>>>(x, Xh, Xl, s, q);
    trred_kernel<<<BB, 256>>>(s, q, tr);

    gram_mma<<<dim3(10, 1, BB), 128, SMEM64>>>(Xh, Xl, s, tr, H, L);

    dim3 g1(20, 1, BB / NBG), g2(20, 2, BB / NBG);
    // slots: A=0 B0=1 B1=2 Y0=3 Y1=4 Z0=5 Z1=6
    ns_mma<0><<<g1, 128, SMEM32>>>(H, L, 0, 1, 3, 0, 1, 3, tr, out);  // Y0 = A@B0
    // iter 1
    ns_mma<1><<<g1, 128, SMEM32>>>(H, L, 1, 3, 2, 1, 3, 2, tr, out);  // B1 = f(B0@Y0)
    ns_mma<0><<<g2, 128, SMEM32>>>(H, L, 3, 2, 4, 2, 1, 5, tr, out);  // Y1=Y0@B1 || Z0=B1@B0
    // iter 2
    ns_mma<1><<<g1, 128, SMEM32>>>(H, L, 5, 4, 1, 5, 4, 1, tr, out);  // B0 = f(Z0@Y1)
    ns_mma<0><<<g2, 128, SMEM32>>>(H, L, 4, 1, 3, 1, 5, 6, tr, out);  // Y0=Y1@B0 || Z1=B0@Z0
    // iter 3
    ns_mma<1><<<g1, 128, SMEM32>>>(H, L, 6, 3, 2, 6, 3, 2, tr, out);  // B1 = f(Z1@Y0)
    ns_mma<0><<<g2, 128, SMEM32>>>(H, L, 3, 2, 4, 2, 6, 5, tr, out);  // Y1=Y0@B1 || Z0=B1@Z1
    // iter 4 (Z update dead -> dropped)
    ns_mma<1><<<g1, 128, SMEM32>>>(H, L, 5, 4, 1, 5, 4, 1, tr, out);  // B0 = f(Z0@Y1)
    ns_mma<2><<<g1, 128, SMEM32>>>(H, L, 4, 1, 0, 4, 1, 0, tr, out);  // triuvec(Y1@B0)
}

// round 12
// speedup vs baseline: 1.1489x; 1.1489x over previous
#include <cuda_runtime.h>
#include <cuda_fp16.h>
#include <math.h>
#include <stdint.h>

#define BB 32
#define CC 256
#define NN 3136
#define OUTC 32896            // 256*257/2
#define MATSZ (BB*CC*CC)
#define XSZ (BB*CC*NN)

#define CHK 32
#define STG64 16384           // gram stage: A(8K)+B(8K)
#define SMEM64 (3*STG64)      // 49152
#define STG32 12288           // ns stage: A(8K)+B(4K)
#define SMEM32 (3*STG32)      // 36864
#define SSCALE 64.0f
#define INVS2 (1.0f/(SSCALE*SSCALE))
#define MP 72                 // transpose-buffer pitch in halves

// gram: 10 upper 64x64 tiles
__device__ __constant__ int c_TI[10] = {0,0,0,0,1,1,1,2,2,3};
__device__ __constant__ int c_TJ[10] = {0,1,2,3,1,2,3,2,3,3};
// ns: 20 tiles 64x32 with j*32 >= i*64
__device__ __constant__ int c_SI[20] = {0,0,0,0,0,0,0,0, 1,1,1,1,1,1, 2,2,2,2, 3,3};
__device__ __constant__ int c_SJ[20] = {0,1,2,3,4,5,6,7, 2,3,4,5,6,7, 4,5,6,7, 6,7};

// ---------------- scratch: matrices stored as hi/lo fp16 pairs ----------------
// slots: A=0 B0=1 B1=2 Y0=3 Y1=4 Z0=5 Z1=6
__device__ __align__(16) __half g_H[7*MATSZ];
__device__ __align__(16) __half g_L[7*MATSZ];
__device__ __align__(16) __half g_Xh[XSZ];
__device__ __align__(16) __half g_Xl[XSZ];
__device__ float g_s[BB*CC];
__device__ float g_q[BB*CC];
__device__ float g_tr[BB];

// ---------------- primitives ----------------
__device__ __forceinline__ uint32_t smem_u32(const void* p) {
    uint32_t a;
    asm("{ .reg .u64 t; cvta.to.shared.u64 t, %1; cvt.u32.u64 %0, t; }" : "=r"(a) : "l"(p));
    return a;
}

__device__ __forceinline__ void mma16(float* c, const unsigned* a, const unsigned* b) {
    asm volatile(
        "mma.sync.aligned.m16n8k16.row.col.f32.f16.f16.f32 "
        "{%0,%1,%2,%3}, {%4,%5,%6,%7}, {%8,%9}, {%0,%1,%2,%3};"
        : "+f"(c[0]), "+f"(c[1]), "+f"(c[2]), "+f"(c[3])
        : "r"(a[0]), "r"(a[1]), "r"(a[2]), "r"(a[3]), "r"(b[0]), "r"(b[1]));
}

__device__ __forceinline__ void ldm4(unsigned r[4], uint32_t a) {
    asm volatile("ldmatrix.sync.aligned.m8n8.x4.shared.b16 {%0,%1,%2,%3}, [%4];"
                 : "=r"(r[0]), "=r"(r[1]), "=r"(r[2]), "=r"(r[3]) : "r"(a));
}

#define CP16(dst, src) \
    asm volatile("cp.async.cg.shared.global [%0], [%1], 16;" :: "r"(dst), "l"(src))
#define CP_COMMIT() asm volatile("cp.async.commit_group;" ::: "memory")
#define CP_WAIT1() asm volatile("cp.async.wait_group 1;" ::: "memory")

__device__ __forceinline__ void split_pair(float v0, float v1, unsigned& hi, unsigned& lo) {
    float s0 = v0 * SSCALE, s1 = v1 * SSCALE;
    __half h0 = __float2half_rn(s0), h1 = __float2half_rn(s1);
    __half l0 = __float2half_rn(s0 - __half2float(h0));
    __half l1 = __float2half_rn(s1 - __half2float(h1));
    __half2 hh = __halves2half2(h0, h1), ll = __halves2half2(l0, l1);
    hi = *(unsigned*)&hh;
    lo = *(unsigned*)&ll;
}

// ================= 64x64 path (gram, pipelined) =================
__device__ __forceinline__ void issue_chunk64(uint32_t dstBase,
                                              const __half* Ah, const __half* Al,
                                              const __half* Bh, const __half* Bl,
                                              int strideH, int k0, int tid) {
#pragma unroll
    for (int i = 0; i < 8; ++i) {
        int n = i * 128 + tid;
        int mat = n >> 9;
        int m = n & 511;
        int row = m >> 3, g = m & 7;
        const __half* hbase = (mat == 0) ? (g < 4 ? Ah : Al) : (g < 4 ? Bh : Bl);
        const __half* src = hbase + (size_t)row * strideH + k0 + 8 * (g & 3);
        uint32_t dst = dstBase + mat * 8192 + row * 128 + ((g ^ (row & 7)) << 4);
        CP16(dst, src);
    }
}

__device__ __forceinline__ void compute_chunk64(uint32_t stBase, float acc[2][4][4],
                                                int wm, int wn, int lane) {
    int lr = lane & 7;
    int lt8 = (lane >> 3) & 1;
    int lkh = (lane >> 4) & 1;
    uint32_t aL = stBase + (wm * 32 + lt8 * 8 + lr) * 128;
    uint32_t bL = stBase + 8192 + (wn * 32 + lkh * 8 + lr) * 128;
#pragma unroll
    for (int ks = 0; ks < 2; ++ks) {
        unsigned ah[2][4], al[2][4], bh[2][4], bl[2][4];
        int gA = ks * 2 + lkh, gB = ks * 2 + lt8;
        ldm4(ah[0], aL + ((gA ^ lr) << 4));
        ldm4(ah[1], aL + 2048 + ((gA ^ lr) << 4));
        ldm4(al[0], aL + (((gA + 4) ^ lr) << 4));
        ldm4(al[1], aL + 2048 + (((gA + 4) ^ lr) << 4));
        ldm4(bh[0], bL + ((gB ^ lr) << 4));
        ldm4(bh[1], bL + 2048 + ((gB ^ lr) << 4));
        ldm4(bl[0], bL + (((gB + 4) ^ lr) << 4));
        ldm4(bl[1], bL + 2048 + (((gB + 4) ^ lr) << 4));
#pragma unroll
        for (int it = 0; it < 2; ++it)
#pragma unroll
            for (int jt = 0; jt < 4; ++jt)
                mma16(acc[it][jt], ah[it], &bh[jt >> 1][(jt & 1) * 2]);
#pragma unroll
        for (int it = 0; it < 2; ++it)
#pragma unroll
            for (int jt = 0; jt < 4; ++jt)
                mma16(acc[it][jt], ah[it], &bl[jt >> 1][(jt & 1) * 2]);
#pragma unroll
        for (int it = 0; it < 2; ++it)
#pragma unroll
            for (int jt = 0; jt < 4; ++jt)
                mma16(acc[it][jt], al[it], &bh[jt >> 1][(jt & 1) * 2]);
    }
}

__device__ __forceinline__ void run_loop64(uint32_t smem_u,
                                           const __half* Ah, const __half* Al,
                                           const __half* Bh, const __half* Bl,
                                           int strideH, int nch, float acc[2][4][4],
                                           int wm, int wn, int lane, int tid) {
    issue_chunk64(smem_u, Ah, Al, Bh, Bl, strideH, 0, tid);
    CP_COMMIT();
    issue_chunk64(smem_u + STG64, Ah, Al, Bh, Bl, strideH, CHK, tid);
    CP_COMMIT();
    int st = 0;
    for (int s = 0; s < nch; ++s) {
        CP_WAIT1();
        __syncthreads();
        if (s + 2 < nch) {
            int st2 = st + 2;
            if (st2 >= 3) st2 -= 3;
            issue_chunk64(smem_u + st2 * STG64, Ah, Al, Bh, Bl, strideH, (s + 2) * CHK, tid);
        }
        CP_COMMIT();
        compute_chunk64(smem_u + st * STG64, acc, wm, wn, lane);
        if (++st == 3) st = 0;
    }
}

// ================= 64x32 path (NS GEMMs, pipelined) =================
__device__ __forceinline__ void issue_chunk32(uint32_t dstBase,
                                              const __half* Ph, const __half* Pl,
                                              const __half* Qh, const __half* Ql,
                                              int k0, int tid) {
#pragma unroll
    for (int i = 0; i < 6; ++i) {
        int n = i * 128 + tid;          // 0..767
        bool isB = n >= 512;
        int m = isB ? n - 512 : n;
        int row = m >> 3, g = m & 7;
        const __half* hbase = isB ? (g < 4 ? Qh : Ql) : (g < 4 ? Ph : Pl);
        const __half* src = hbase + (size_t)row * CC + k0 + 8 * (g & 3);
        uint32_t dst = dstBase + (isB ? 8192 : 0) + row * 128 + ((g ^ (row & 7)) << 4);
        CP16(dst, src);
    }
}

__device__ __forceinline__ void compute_chunk32(uint32_t stBase, float acc[2][2][4],
                                                int wm, int wn, int lane) {
    int lr = lane & 7;
    int lt8 = (lane >> 3) & 1;
    int lkh = (lane >> 4) & 1;
    uint32_t aL = stBase + (wm * 32 + lt8 * 8 + lr) * 128;
    uint32_t bL = stBase + 8192 + (wn * 16 + lkh * 8 + lr) * 128;
#pragma unroll
    for (int ks = 0; ks < 2; ++ks) {
        unsigned ah[2][4], al[2][4], bh[4], bl[4];
        int gA = ks * 2 + lkh, gB = ks * 2 + lt8;
        ldm4(ah[0], aL + ((gA ^ lr) << 4));
        ldm4(ah[1], aL + 2048 + ((gA ^ lr) << 4));
        ldm4(al[0], aL + (((gA + 4) ^ lr) << 4));
        ldm4(al[1], aL + 2048 + (((gA + 4) ^ lr) << 4));
        ldm4(bh, bL + ((gB ^ lr) << 4));
        ldm4(bl, bL + (((gB + 4) ^ lr) << 4));
#pragma unroll
        for (int it = 0; it < 2; ++it)
#pragma unroll
            for (int jt = 0; jt < 2; ++jt)
                mma16(acc[it][jt], ah[it], &bh[jt * 2]);
#pragma unroll
        for (int it = 0; it < 2; ++it)
#pragma unroll
            for (int jt = 0; jt < 2; ++jt)
                mma16(acc[it][jt], ah[it], &bl[jt * 2]);
#pragma unroll
        for (int it = 0; it < 2; ++it)
#pragma unroll
            for (int jt = 0; jt < 2; ++jt)
                mma16(acc[it][jt], al[it], &bh[jt * 2]);
    }
}

__device__ __forceinline__ void run_loop32(uint32_t smem_u,
                                           const __half* Ph, const __half* Pl,
                                           const __half* Qh, const __half* Ql,
                                           float acc[2][2][4],
                                           int wm, int wn, int lane, int tid) {
    const int nch = CC / CHK;   // 8
    issue_chunk32(smem_u, Ph, Pl, Qh, Ql, 0, tid);
    CP_COMMIT();
    issue_chunk32(smem_u + STG32, Ph, Pl, Qh, Ql, CHK, tid);
    CP_COMMIT();
    int st = 0;
#pragma unroll
    for (int s = 0; s < nch; ++s) {
        CP_WAIT1();
        __syncthreads();
        if (s + 2 < nch) {
            int st2 = st + 2;
            if (st2 >= 3) st2 -= 3;
            issue_chunk32(smem_u + st2 * STG32, Ph, Pl, Qh, Ql, (s + 2) * CHK, tid);
        }
        CP_COMMIT();
        compute_chunk32(smem_u + st * STG32, acc, wm, wn, lane);
        if (++st == 3) st = 0;
    }
}

// ---------------- splitx + trace ----------------
__global__ __launch_bounds__(256) void splitx_kernel(const float* __restrict__ X,
                                                     __half* __restrict__ Xh,
                                                     __half* __restrict__ Xl,
                                                     float* __restrict__ s,
                                                     float* __restrict__ q) {
    int c = blockIdx.x, b = blockIdx.y;
    size_t base = ((size_t)b * CC + c) * NN;
    const float4* row = (const float4*)(X + base);
    float acc = 0.f, accq = 0.f;
    for (int i = threadIdx.x; i < NN / 4; i += 256) {
        float4 v = row[i];
        acc += v.x + v.y + v.z + v.w;
        accq += v.x * v.x + v.y * v.y + v.z * v.z + v.w * v.w;
        unsigned h0, l0, h1, l1;
        split_pair(v.x, v.y, h0, l0);
        split_pair(v.z, v.w, h1, l1);
        *(uint2*)(Xh + base + i * 4) = make_uint2(h0, h1);
        *(uint2*)(Xl + base + i * 4) = make_uint2(l0, l1);
    }
    __shared__ float ss[256], sq[256];
    ss[threadIdx.x] = acc;
    sq[threadIdx.x] = accq;
    __syncthreads();
    for (int st = 128; st > 0; st >>= 1) {
        if (threadIdx.x < st) {
            ss[threadIdx.x] += ss[threadIdx.x + st];
            sq[threadIdx.x] += sq[threadIdx.x + st];
        }
        __syncthreads();
    }
    if (threadIdx.x == 0) {
        s[b * CC + c] = ss[0];
        q[b * CC + c] = sq[0];
    }
}

__global__ __launch_bounds__(256) void trred_kernel(const float* __restrict__ s,
                                                    const float* __restrict__ q,
                                                    float* __restrict__ tr) {
    int b = blockIdx.x, c = threadIdx.x;
    const float inv_n = 1.0f / (float)NN;
    const float inv_n2 = inv_n * inv_n;
    float sv = s[b * CC + c];
    float v = q[b * CC + c] * inv_n - sv * sv * inv_n2;
    __shared__ float sm[256];
    sm[c] = v;
    __syncthreads();
    for (int st = 128; st > 0; st >>= 1) {
        if (c < st) sm[c] += sm[c + st];
        __syncthreads();
    }
    if (c == 0) tr[b] = sm[0];
}

// ---------------- gram ----------------
__global__ __launch_bounds__(128, 4) void gram_mma(const __half* __restrict__ Xh,
                                                   const __half* __restrict__ Xl,
                                                   const float* __restrict__ sv,
                                                   const float* __restrict__ trv,
                                                   __half* __restrict__ H,
                                                   __half* __restrict__ L) {
    extern __shared__ unsigned swm[];
    uint32_t smem_u = smem_u32(swm);
    int b = blockIdx.z, tile = blockIdx.x;
    int i0 = c_TI[tile] * 64, j0 = c_TJ[tile] * 64;
    bool mirror = (i0 != j0);
    int tid = threadIdx.x;
    int warp = tid >> 5, lane = tid & 31;
    int wm = warp >> 1, wn = warp & 1, g = lane >> 2, t = lane & 3;
    float acc[2][4][4] = {};

    const __half* Xhb = Xh + (size_t)b * CC * NN;
    const __half* Xlb = Xl + (size_t)b * CC * NN;
    run_loop64(smem_u, Xhb + (size_t)i0 * NN, Xlb + (size_t)i0 * NN,
               Xhb + (size_t)j0 * NN, Xlb + (size_t)j0 * NN, NN, NN / CHK,
               acc, wm, wn, lane, tid);

    __syncthreads();                 // stage smem now reusable as transpose buffer
    __half* M = (__half*)swm;        // [mat*2+comp][64][MP]

    const float inv_n = 1.0f / (float)NN;
    const float inv_n2 = inv_n * inv_n;
    float invtr = 1.0f / trv[b];
    float c1 = INVS2 * inv_n * invtr;
    float c2 = inv_n2 * invtr;
    __half* Ah = H + (size_t)b * CC * CC;
    __half* Al = L + (size_t)b * CC * CC;
    __half* B0h = H + (size_t)MATSZ + (size_t)b * CC * CC;
    __half* B0l = L + (size_t)MATSZ + (size_t)b * CC * CC;
#pragma unroll
    for (int it = 0; it < 2; ++it)
#pragma unroll
        for (int jt = 0; jt < 4; ++jt) {
            int gi = i0 + wm * 32 + it * 16 + g;
            int gj = j0 + wn * 32 + jt * 8 + 2 * t;
            float* ca = acc[it][jt];
#pragma unroll
            for (int h = 0; h < 2; ++h) {
                int r = gi + h * 8;
                float si = sv[b * CC + r];
                float a0 = ca[h * 2 + 0] * c1 - si * sv[b * CC + gj] * c2;
                float a1 = ca[h * 2 + 1] * c1 - si * sv[b * CC + gj + 1] * c2;
                float w0 = (r == gj ? 1.5f : 0.0f) - 0.5f * a0;
                float w1 = (r == gj + 1 ? 1.5f : 0.0f) - 0.5f * a1;
                unsigned hiA, loA, hiB, loB;
                split_pair(a0, a1, hiA, loA);
                *(unsigned*)&Ah[(size_t)r * CC + gj] = hiA;
                *(unsigned*)&Al[(size_t)r * CC + gj] = loA;
                split_pair(w0, w1, hiB, loB);
                *(unsigned*)&B0h[(size_t)r * CC + gj] = hiB;
                *(unsigned*)&B0l[(size_t)r * CC + gj] = loB;
                if (mirror) {
                    int r_l = r - i0, c_l = gj - j0;
                    __half2 x;
                    x = *(__half2*)&hiA;
                    M[(0 * 64 + c_l) * MP + r_l] = __low2half(x);
                    M[(0 * 64 + c_l + 1) * MP + r_l] = __high2half(x);
                    x = *(__half2*)&loA;
                    M[(1 * 64 + c_l) * MP + r_l] = __low2half(x);
                    M[(1 * 64 + c_l + 1) * MP + r_l] = __high2half(x);
                    x = *(__half2*)&hiB;
                    M[(2 * 64 + c_l) * MP + r_l] = __low2half(x);
                    M[(2 * 64 + c_l + 1) * MP + r_l] = __high2half(x);
                    x = *(__half2*)&loB;
                    M[(3 * 64 + c_l) * MP + r_l] = __low2half(x);
                    M[(3 * 64 + c_l + 1) * MP + r_l] = __high2half(x);
                }
            }
        }
    if (mirror) {
        __syncthreads();
#pragma unroll
        for (int u = 0; u < 2; ++u) {
            int unit = tid + u * 128;        // 0..255
            int mc = unit >> 6;              // 0:Ah 1:Al 2:B0h 3:B0l
            int c_l = unit & 63;
            const uint4* srcv = (const uint4*)(M + (mc * 64 + c_l) * MP);
            __half* dstp = (mc == 0) ? Ah : (mc == 1) ? Al : (mc == 2) ? B0h : B0l;
            uint4* dstv = (uint4*)(dstp + (size_t)(j0 + c_l) * CC + i0);
#pragma unroll
            for (int w2 = 0; w2 < 8; ++w2) dstv[w2] = srcv[w2];
        }
    }
}

// ---------------- NS GEMM (64x32 tiles, slot-indexed, optional pair via grid.y) ----------------
// EPI 0: C=P@Q     EPI 1: C=1.5I-0.5(P@Q)     EPI 2: triuvec(P@Q * sqrt(tr))
template <int EPI>
__global__ __launch_bounds__(128, 5) void ns_mma(__half* __restrict__ H,
                                                 __half* __restrict__ L,
                                                 int p0, int q0, int cs0,
                                                 int p1, int q1, int cs1,
                                                 const float* __restrict__ trv,
                                                 float* __restrict__ outg) {
    extern __shared__ unsigned swm[];
    uint32_t smem_u = smem_u32(swm);
    int b = blockIdx.z, tile = blockIdx.x;
    int sel = blockIdx.y;
    int ps = sel ? p1 : p0, qs = sel ? q1 : q0, cs = sel ? cs1 : cs0;
    int i0 = c_SI[tile] * 64, j0 = c_SJ[tile] * 32;
    int tid = threadIdx.x;
    int warp = tid >> 5, lane = tid & 31;
    int wm = warp >> 1, wn = warp & 1, g = lane >> 2, t = lane & 3;
    float acc[2][2][4] = {};

    size_t mb = (size_t)b * CC * CC;
    const __half* Ph = H + (size_t)ps * MATSZ + mb + (size_t)i0 * CC;
    const __half* Pl = L + (size_t)ps * MATSZ + mb + (size_t)i0 * CC;
    const __half* Qh = H + (size_t)qs * MATSZ + mb + (size_t)j0 * CC;
    const __half* Ql = L + (size_t)qs * MATSZ + mb + (size_t)j0 * CC;
    run_loop32(smem_u, Ph, Pl, Qh, Ql, acc, wm, wn, lane, tid);

    __half* Ch = H + (size_t)cs * MATSZ + mb;
    __half* Cl = L + (size_t)cs * MATSZ + mb;

    if (EPI == 2) {
        float scale = sqrtf(trv[b]) * INVS2;
#pragma unroll
        for (int it = 0; it < 2; ++it)
#pragma unroll
            for (int jt = 0; jt < 2; ++jt) {
                int gi = i0 + wm * 32 + it * 16 + g;
                int gj = j0 + wn * 16 + jt * 8 + 2 * t;
                float* ca = acc[it][jt];
#pragma unroll
                for (int h = 0; h < 2; ++h) {
                    int r = gi + h * 8;
                    float v0 = ca[h * 2 + 0] * scale, v1 = ca[h * 2 + 1] * scale;
                    int base = r * CC - (r * (r - 1)) / 2 - r;
                    if (gj >= r) outg[(size_t)b * OUTC + base + gj] = v0;
                    if (gj + 1 >= r) outg[(size_t)b * OUTC + base + gj + 1] = v1;
                }
            }
    } else {
        __syncthreads();             // stage smem reusable as transpose buffer
        __half* M = (__half*)swm;    // [comp(2)][32][MP]
#pragma unroll
        for (int it = 0; it < 2; ++it)
#pragma unroll
            for (int jt = 0; jt < 2; ++jt) {
                int gi = i0 + wm * 32 + it * 16 + g;
                int gj = j0 + wn * 16 + jt * 8 + 2 * t;
                float* ca = acc[it][jt];
#pragma unroll
                for (int h = 0; h < 2; ++h) {
                    int r = gi + h * 8;
                    float v0 = ca[h * 2 + 0] * INVS2, v1 = ca[h * 2 + 1] * INVS2;
                    if (EPI == 1) {
                        v0 = (r == gj ? 1.5f : 0.0f) - 0.5f * v0;
                        v1 = (r == gj + 1 ? 1.5f : 0.0f) - 0.5f * v1;
                    }
                    unsigned hi, lo;
                    split_pair(v0, v1, hi, lo);
                    *(unsigned*)&Ch[(size_t)r * CC + gj] = hi;
                    *(unsigned*)&Cl[(size_t)r * CC + gj] = lo;
                    int r_l = r - i0, c_l = gj - j0;
                    __half2 x = *(__half2*)&hi;
                    M[c_l * MP + r_l] = __low2half(x);
                    M[(c_l + 1) * MP + r_l] = __high2half(x);
                    x = *(__half2*)&lo;
                    M[(32 + c_l) * MP + r_l] = __low2half(x);
                    M[(32 + c_l + 1) * MP + r_l] = __high2half(x);
                }
            }
        __syncthreads();
        int unit = tid >> 1;             // 0..63
        int comp = unit >> 5, c_l = unit & 31;
        int seg = (tid & 1) * 32;        // halves
        const uint4* srcv = (const uint4*)(M + (comp * 32 + c_l) * MP + seg);
        __half* dstp = (comp ? Cl : Ch) + (size_t)(j0 + c_l) * CC + i0 + seg;
        uint4* dstv = (uint4*)dstp;
        dstv[0] = srcv[0];
        dstv[1] = srcv[1];
        dstv[2] = srcv[2];
        dstv[3] = srcv[3];
    }
}

// ---------------- launch ----------------
extern "C" void kernel_launch(void* const* d_in, const int* in_sizes, int n_in,
                              void* d_out, int out_size) {
    const float* x = (const float*)d_in[0];
    float* out = (float*)d_out;

    __half *H, *L, *Xh, *Xl;
    float *s, *q, *tr;
    cudaGetSymbolAddress((void**)&H, g_H);
    cudaGetSymbolAddress((void**)&L, g_L);
    cudaGetSymbolAddress((void**)&Xh, g_Xh);
    cudaGetSymbolAddress((void**)&Xl, g_Xl);
    cudaGetSymbolAddress((void**)&s, g_s);
    cudaGetSymbolAddress((void**)&q, g_q);
    cudaGetSymbolAddress((void**)&tr, g_tr);

    cudaFuncSetAttribute(gram_mma, cudaFuncAttributeMaxDynamicSharedMemorySize, SMEM64);
    cudaFuncSetAttribute(ns_mma<0>, cudaFuncAttributeMaxDynamicSharedMemorySize, SMEM32);
    cudaFuncSetAttribute(ns_mma<1>, cudaFuncAttributeMaxDynamicSharedMemorySize, SMEM32);
    cudaFuncSetAttribute(ns_mma<2>, cudaFuncAttributeMaxDynamicSharedMemorySize, SMEM32);

    splitx_kernel<<<dim3(CC, BB), 256>>>(x, Xh, Xl, s, q);
    trred_kernel<<<BB, 256>>>(s, q, tr);

    gram_mma<<<dim3(10, 1, BB), 128, SMEM64>>>(Xh, Xl, s, tr, H, L);

    dim3 g1(20, 1, BB), g2(20, 2, BB);
    // slots: A=0 B0=1 B1=2 Y0=3 Y1=4 Z0=5 Z1=6
    ns_mma<0><<<g1, 128, SMEM32>>>(H, L, 0, 1, 3, 0, 1, 3, tr, out);  // Y0 = A@B0
    // iter 1
    ns_mma<1><<<g1, 128, SMEM32>>>(H, L, 1, 3, 2, 1, 3, 2, tr, out);  // B1 = f(B0@Y0)
    ns_mma<0><<<g2, 128, SMEM32>>>(H, L, 3, 2, 4, 2, 1, 5, tr, out);  // Y1=Y0@B1 || Z0=B1@B0
    // iter 2
    ns_mma<1><<<g1, 128, SMEM32>>>(H, L, 5, 4, 1, 5, 4, 1, tr, out);  // B0 = f(Z0@Y1)
    ns_mma<0><<<g2, 128, SMEM32>>>(H, L, 4, 1, 3, 1, 5, 6, tr, out);  // Y0=Y1@B0 || Z1=B0@Z0
    // iter 3
    ns_mma<1><<<g1, 128, SMEM32>>>(H, L, 6, 3, 2, 6, 3, 2, tr, out);  // B1 = f(Z1@Y0)
    ns_mma<0><<<g2, 128, SMEM32>>>(H, L, 3, 2, 4, 2, 6, 5, tr, out);  // Y1=Y0@B1 || Z0=B1@Z1
    // iter 4 (Z update dead -> dropped)
    ns_mma<1><<<g1, 128, SMEM32>>>(H, L, 5, 4, 1, 5, 4, 1, tr, out);  // B0 = f(Z0@Y1)
    ns_mma<2><<<g1, 128, SMEM32>>>(H, L, 4, 1, 0, 4, 1, 0, tr, out);  // triuvec(Y1@B0)
}